// round 16
// baseline (speedup 1.0000x reference)
#include <cuda_runtime.h>
#include <math.h>
#include <stdint.h>

#define Bb   2
#define Ll   1024
#define Dd   256
#define Kk   64
#define K2   128          // 2K (re|im concat)
#define NTOK (Bb*Ll)      // 2048
#define CH   128          // scan chunk length
#define NC   (Ll/CH)      // 8
#define NCH  (Bb*NC)      // 16
#define EPSv 1e-5f
#define PIv  3.14159265358979323846f

// ------------------------- scratch (static device memory) -------------------
__device__ float g_hk  [NTOK*Dd];
__device__ float g_hq  [NTOK*Dd];
__device__ float g_kk  [NTOK*K2];
__device__ float g_qq  [NTOK*K2];
__device__ float g_V   [NTOK*Dd];
__device__ float g_G   [NCH*K2*Dd];
__device__ float g_A   [NCH*CH*CH];
__device__ float g_ret [NTOK*Dd];
__device__ float g_rn  [NTOK*Dd];

// ------------------------- tf32 mma primitives ------------------------------
__device__ __forceinline__ float to_tf32(float x) {
    uint32_t u;
    asm("cvt.rna.tf32.f32 %0, %1;" : "=r"(u) : "f"(x));
    return __uint_as_float(u);
}
__device__ __forceinline__ float4 tf32x4(float4 v) {
    return make_float4(to_tf32(v.x), to_tf32(v.y), to_tf32(v.z), to_tf32(v.w));
}

__device__ __forceinline__ void mma8(float c[4], const uint32_t a[4], const uint32_t b[2]) {
    asm volatile(
        "mma.sync.aligned.m16n8k8.row.col.f32.tf32.tf32.f32 "
        "{%0,%1,%2,%3}, {%4,%5,%6,%7}, {%8,%9}, {%0,%1,%2,%3};"
        : "+f"(c[0]), "+f"(c[1]), "+f"(c[2]), "+f"(c[3])
        : "r"(a[0]), "r"(a[1]), "r"(a[2]), "r"(a[3]), "r"(b[0]), "r"(b[1]));
}

// ---- A in [m][20] row-major, B in [k][72] k-major (conflict-free frags) ----
template<int MT>
__device__ __forceinline__ void mma_mk(const float* As, const float* Bs,
                                       int wm, int wn, int g, int t, float (*c)[4][4])
{
    #pragma unroll
    for (int ks = 0; ks < 16; ks += 8) {
        uint32_t a[MT][4], b[4][2];
        #pragma unroll
        for (int mt = 0; mt < MT; mt++) {
            int m0 = wm + mt * 16 + g;
            a[mt][0] = __float_as_uint(As[m0 * 20 + ks + t]);
            a[mt][1] = __float_as_uint(As[(m0 + 8) * 20 + ks + t]);
            a[mt][2] = __float_as_uint(As[m0 * 20 + ks + t + 4]);
            a[mt][3] = __float_as_uint(As[(m0 + 8) * 20 + ks + t + 4]);
        }
        #pragma unroll
        for (int nt = 0; nt < 4; nt++) {
            int n0 = wn + nt * 8 + g;
            b[nt][0] = __float_as_uint(Bs[(ks + t) * 72 + n0]);
            b[nt][1] = __float_as_uint(Bs[(ks + t + 4) * 72 + n0]);
        }
        #pragma unroll
        for (int mt = 0; mt < MT; mt++)
            #pragma unroll
            for (int nt = 0; nt < 4; nt++)
                mma8(c[mt][nt], a[mt], b[nt]);
    }
}

// ---- A in [m][20], B in [n][20] (transposed-B operand) ---------------------
template<int MT>
__device__ __forceinline__ void mma_mk_tb(const float* As, const float* Bs,
                                          int wm, int wn, int g, int t, float (*c)[4][4])
{
    #pragma unroll
    for (int ks = 0; ks < 16; ks += 8) {
        uint32_t a[MT][4], b[4][2];
        #pragma unroll
        for (int mt = 0; mt < MT; mt++) {
            int m0 = wm + mt * 16 + g;
            a[mt][0] = __float_as_uint(As[m0 * 20 + ks + t]);
            a[mt][1] = __float_as_uint(As[(m0 + 8) * 20 + ks + t]);
            a[mt][2] = __float_as_uint(As[m0 * 20 + ks + t + 4]);
            a[mt][3] = __float_as_uint(As[(m0 + 8) * 20 + ks + t + 4]);
        }
        #pragma unroll
        for (int nt = 0; nt < 4; nt++) {
            int n0 = wn + nt * 8 + g;
            b[nt][0] = __float_as_uint(Bs[n0 * 20 + ks + t]);
            b[nt][1] = __float_as_uint(Bs[n0 * 20 + ks + t + 4]);
        }
        #pragma unroll
        for (int mt = 0; mt < MT; mt++)
            #pragma unroll
            for (int nt = 0; nt < 4; nt++)
                mma8(c[mt][nt], a[mt], b[nt]);
    }
}

// ---- both operands [k][LD] k-major -----------------------------------------
template<int MT, int LDA, int LDB>
__device__ __forceinline__ void mma_kk(const float* As, const float* Bs,
                                       int wm, int wn, int g, int t, float (*c)[4][4])
{
    #pragma unroll
    for (int ks = 0; ks < 16; ks += 8) {
        uint32_t a[MT][4], b[4][2];
        #pragma unroll
        for (int mt = 0; mt < MT; mt++) {
            int m0 = wm + mt * 16 + g;
            a[mt][0] = __float_as_uint(As[(ks + t) * LDA + m0]);
            a[mt][1] = __float_as_uint(As[(ks + t) * LDA + m0 + 8]);
            a[mt][2] = __float_as_uint(As[(ks + t + 4) * LDA + m0]);
            a[mt][3] = __float_as_uint(As[(ks + t + 4) * LDA + m0 + 8]);
        }
        #pragma unroll
        for (int nt = 0; nt < 4; nt++) {
            int n0 = wn + nt * 8 + g;
            b[nt][0] = __float_as_uint(Bs[(ks + t) * LDB + n0]);
            b[nt][1] = __float_as_uint(Bs[(ks + t + 4) * LDB + n0]);
        }
        #pragma unroll
        for (int mt = 0; mt < MT; mt++)
            #pragma unroll
            for (int nt = 0; nt < 4; nt++)
                mma8(c[mt][nt], a[mt], b[nt]);
    }
}

// ------------------------- encoder pre-GEMM (z=3) ----------------------------
// CTA 64x64 (MT=1), 256 threads, grid (4, 32, 3) = 384 CTAs. High occupancy.
__global__ void __launch_bounds__(256)
enc_gemm_kernel(const float* __restrict__ x,
                const float* __restrict__ pos_k, const float* __restrict__ pos_q,
                const float* __restrict__ w1_k, const float* __restrict__ b1_k,
                const float* __restrict__ w1_q, const float* __restrict__ b1_q,
                const float* __restrict__ wv,   const float* __restrict__ bv,
                float* __restrict__ hk, float* __restrict__ hq, float* __restrict__ V)
{
    const int z = blockIdx.z;
    const float* W;  const float* bias; const float* pos; float* C;
    if (z == 0)      { W = w1_k; bias = b1_k; pos = pos_k; C = hk; }
    else if (z == 1) { W = w1_q; bias = b1_q; pos = pos_q; C = hq; }
    else             { W = wv;   bias = bv;   pos = nullptr; C = V; }

    __shared__ __align__(16) float As[2][64 * 20];
    __shared__ __align__(16) float Bs[2][16 * 72];

    const int tid  = threadIdx.x;
    const int lane = tid & 31, wid = tid >> 5;
    const int wm = (wid & 3) * 16, wn = (wid >> 2) * 32;
    const int g = lane >> 2, t = lane & 3;
    const int rowTile = blockIdx.y * 64;
    const int colTile = blockIdx.x * 64;

    float c[1][4][4] = {};
    const int m = tid >> 2, akq = (tid & 3) * 4;
    const int bk = tid >> 4, bn = (tid & 15) * 4;
    const int row = rowTile + m;
    const int prow = row & (Ll - 1);
    float4 av, bv2;

    auto LDG = [&](int k0) {
        av = *(const float4*)&x[(long)row * Dd + k0 + akq];
        if (pos) {
            float4 p = *(const float4*)&pos[(long)prow * Dd + k0 + akq];
            av.x += p.x; av.y += p.y; av.z += p.z; av.w += p.w;
        }
        bv2 = *(const float4*)&W[(long)(k0 + bk) * Dd + colTile + bn];
    };
    auto STS = [&](int s) {
        *(float4*)&As[s][m * 20 + akq] = tf32x4(av);
        *(float4*)&Bs[s][bk * 72 + bn] = tf32x4(bv2);
    };

    LDG(0); STS(0); __syncthreads();
    #pragma unroll 1
    for (int ti = 0; ti < 16; ti++) {
        if (ti + 1 < 16) LDG((ti + 1) * 16);
        mma_mk<1>(As[ti & 1], Bs[ti & 1], wm, wn, g, t, c);
        if (ti + 1 < 16) { STS((ti + 1) & 1); __syncthreads(); }
    }

    #pragma unroll
    for (int nt = 0; nt < 4; nt++) {
        int col = colTile + wn + nt * 8 + 2 * t;
        #pragma unroll
        for (int dr = 0; dr < 2; dr++) {
            int r = rowTile + wm + g + dr * 8;
            float v0 = c[0][nt][dr * 2 + 0] + bias[col];
            float v1 = c[0][nt][dr * 2 + 1] + bias[col + 1];
            if (z < 2) {
                v0 = 0.5f * v0 * (1.0f + erff(v0 * 0.70710678118654752440f));
                v1 = 0.5f * v1 * (1.0f + erff(v1 * 0.70710678118654752440f));
            }
            *(float2*)&C[(long)r * Dd + col] = make_float2(v0, v1);
        }
    }
}

// ------------------------- fused head GEMMs + phasor (z=2) -------------------
struct P4 { float4 u; };
__device__ __forceinline__ void ldgB_kn(P4& p, const float* __restrict__ B,
                                        int ld, int colTile, int k0, int tid) {
    int k = tid >> 4, nq = (tid & 15) * 4;
    p.u = *(const float4*)&B[(long)(k0 + k) * ld + colTile + nq];
}
__device__ __forceinline__ void stsB_kn68(float* Bs, const P4& p, int tid) {
    int k = tid >> 4, nq = (tid & 15) * 4;
    *(float4*)&Bs[k * 68 + nq] = tf32x4(p.u);
}

__global__ void __launch_bounds__(256)
phasor_gemm_kernel(const float* __restrict__ x,
                   const float* __restrict__ pos_k, const float* __restrict__ pos_q,
                   const float* __restrict__ hk,   const float* __restrict__ hq,
                   const float* __restrict__ w2_k, const float* __restrict__ b2_k,
                   const float* __restrict__ wa_k, const float* __restrict__ ba_k,
                   const float* __restrict__ w2_q, const float* __restrict__ b2_q,
                   const float* __restrict__ wa_q, const float* __restrict__ ba_q,
                   float* __restrict__ kk, float* __restrict__ qq)
{
    const int z = blockIdx.z;
    const float* h   = z ? hq    : hk;
    const float* pos = z ? pos_q : pos_k;
    const float* W2  = z ? w2_q  : w2_k;
    const float* B2  = z ? b2_q  : b2_k;
    const float* Wa  = z ? wa_q  : wa_k;
    const float* Ba  = z ? ba_q  : ba_k;
    float* out       = z ? qq    : kk;

    __shared__ __align__(16) float Ah[2][16 * 68];
    __shared__ __align__(16) float Ax[2][16 * 68];
    __shared__ __align__(16) float Bp[2][16 * 68];
    __shared__ __align__(16) float Bm[2][16 * 68];

    const int tid  = threadIdx.x;
    const int lane = tid & 31, wid = tid >> 5;
    const int wm = (wid & 3) * 16, wn = (wid >> 2) * 32;
    const int g = lane >> 2, t = lane & 3;
    const int rowTile = blockIdx.y * 64;

    float cP[1][4][4] = {};
    float cA[1][4][4] = {};

    const int am = tid >> 2, akq = (tid & 3) * 4;
    const int arow = rowTile + am;
    const int prow = arow & (Ll - 1);
    float4 vh, vx, vp; P4 p2, pm;

    auto LDG = [&](int k0) {
        vh = *(const float4*)&h[(long)arow * Dd + k0 + akq];
        vx = *(const float4*)&x[(long)arow * Dd + k0 + akq];
        vp = *(const float4*)&pos[(long)prow * Dd + k0 + akq];
        ldgB_kn(p2, W2, Kk, 0, k0, tid);
        ldgB_kn(pm, Wa, Kk, 0, k0, tid);
    };
    auto STS = [&](int nb) {
        Ah[nb][(akq + 0) * 68 + am] = to_tf32(vh.x);
        Ah[nb][(akq + 1) * 68 + am] = to_tf32(vh.y);
        Ah[nb][(akq + 2) * 68 + am] = to_tf32(vh.z);
        Ah[nb][(akq + 3) * 68 + am] = to_tf32(vh.w);
        Ax[nb][(akq + 0) * 68 + am] = to_tf32(vx.x + vp.x);
        Ax[nb][(akq + 1) * 68 + am] = to_tf32(vx.y + vp.y);
        Ax[nb][(akq + 2) * 68 + am] = to_tf32(vx.z + vp.z);
        Ax[nb][(akq + 3) * 68 + am] = to_tf32(vx.w + vp.w);
        stsB_kn68(Bp[nb], p2, tid);
        stsB_kn68(Bm[nb], pm, tid);
    };

    LDG(0); STS(0);
    __syncthreads();

    const int T = Dd >> 4;
    #pragma unroll 1
    for (int ti = 0; ti < T; ti++) {
        if (ti + 1 < T) LDG((ti + 1) << 4);
        mma_kk<1, 68, 68>(Ah[ti & 1], Bp[ti & 1], wm, wn, g, t, cP);
        mma_kk<1, 68, 68>(Ax[ti & 1], Bm[ti & 1], wm, wn, g, t, cA);
        if (ti + 1 < T) { STS((ti + 1) & 1); __syncthreads(); }
    }

    #pragma unroll
    for (int nt = 0; nt < 4; nt++) {
        int col = wn + nt * 8 + 2 * t;
        #pragma unroll
        for (int dr = 0; dr < 2; dr++) {
            int n = rowTile + wm + g + dr * 8;
            #pragma unroll
            for (int dc = 0; dc < 2; dc++) {
                int cc = col + dc;
                float p = cP[0][nt][dr * 2 + dc] + B2[cc];
                float a = cA[0][nt][dr * 2 + dc] + Ba[cc];
                float ph = tanhf(p) * PIv;
                float sp = fmaxf(a, 0.0f) + log1pf(expf(-fabsf(a)));
                float amp = sp + 0.1f;
                float s, cs;
                sincosf(ph, &s, &cs);
                out[(long)n * K2 + cc]      = amp * cs;
                out[(long)n * K2 + Kk + cc] = amp * s;
            }
        }
    }
}

// ------------------------- merged G + masked-A kernel (192 CTAs) -------------
__global__ void __launch_bounds__(256)
gamask_kernel(const float* __restrict__ kk, const float* __restrict__ qq,
              const float* __restrict__ V,
              float* __restrict__ G, float* __restrict__ Amat)
{
    __shared__ __align__(16) float SA[2][1280];
    __shared__ __align__(16) float SB[2][1280];

    const int tid  = threadIdx.x;
    const int lane = tid & 31, wid = tid >> 5;
    const int wm = (wid & 3) * 16, wn = (wid >> 2) * 32;
    const int g = lane >> 2, t = lane & 3;
    const int z = blockIdx.z;

    if (z < 128) {
        const int chunk = z >> 3, sub = z & 7;
        const int r0 = (sub >> 2) * 64;        // K2 half
        const int colTile = (sub & 3) * 64;    // D slice
        const float* Kb = kk + (long)chunk * CH * K2;
        const float* Vb = V  + (long)chunk * CH * Dd;
        float*       Gb = G  + (long)chunk * K2 * Dd;

        float c[1][4][4] = {};
        const int k = tid >> 4, aq = (tid & 15) * 4;
        float4 av, bv;

        auto LDG = [&](int k0) {
            av = *(const float4*)&Kb[(long)(k0 + k) * K2 + r0 + aq];
            bv = *(const float4*)&Vb[(long)(k0 + k) * Dd + colTile + aq];
        };
        auto STS = [&](int s) {
            *(float4*)&SA[s][k * 72 + aq] = tf32x4(av);
            *(float4*)&SB[s][k * 72 + aq] = tf32x4(bv);
        };

        LDG(0); STS(0); __syncthreads();
        #pragma unroll 1
        for (int ti = 0; ti < 8; ti++) {
            if (ti + 1 < 8) LDG((ti + 1) * 16);
            mma_kk<1, 72, 72>(SA[ti & 1], SB[ti & 1], wm, wn, g, t, c);
            if (ti + 1 < 8) { STS((ti + 1) & 1); __syncthreads(); }
        }

        #pragma unroll
        for (int nt = 0; nt < 4; nt++) {
            int col = colTile + wn + nt * 8 + 2 * t;
            #pragma unroll
            for (int dr = 0; dr < 2; dr++) {
                int r = r0 + wm + g + dr * 8;
                *(float2*)&Gb[(long)r * Dd + col] =
                    make_float2(c[0][nt][dr * 2 + 0], c[0][nt][dr * 2 + 1]);
            }
        }
    } else {
        const int idx = z - 128;
        const int chunk = idx >> 2, sub = idx & 3;
        const int rowTile = (sub >> 1) * 64;
        const int colTile = (sub & 1) * 64;
        const float* Qb = qq + (long)chunk * CH * K2;
        const float* Kb = kk + (long)chunk * CH * K2;
        float*       Cb = Amat + (long)chunk * CH * CH;

        float c[1][4][4] = {};
        const int m = tid >> 2, kq = (tid & 3) * 4;
        float4 av, bv;

        auto LDG = [&](int k0) {
            av = *(const float4*)&Qb[(long)(rowTile + m) * K2 + k0 + kq];
            bv = *(const float4*)&Kb[(long)(colTile + m) * K2 + k0 + kq];
        };
        auto STS = [&](int s) {
            *(float4*)&SA[s][m * 20 + kq] = tf32x4(av);
            *(float4*)&SB[s][m * 20 + kq] = tf32x4(bv);
        };

        LDG(0); STS(0); __syncthreads();
        #pragma unroll 1
        for (int ti = 0; ti < 8; ti++) {
            if (ti + 1 < 8) LDG((ti + 1) * 16);
            mma_mk_tb<1>(SA[ti & 1], SB[ti & 1], wm, wn, g, t, c);
            if (ti + 1 < 8) { STS((ti + 1) & 1); __syncthreads(); }
        }

        #pragma unroll
        for (int nt = 0; nt < 4; nt++) {
            int col = colTile + wn + nt * 8 + 2 * t;
            #pragma unroll
            for (int dr = 0; dr < 2; dr++) {
                int r = rowTile + wm + g + dr * 8;
                float v0 = (col     > r) ? 0.0f : c[0][nt][dr * 2 + 0];
                float v1 = (col + 1 > r) ? 0.0f : c[0][nt][dr * 2 + 1];
                *(float2*)&Cb[(long)r * CH + col] = make_float2(v0, v1);
            }
        }
    }
}

// ------------------------- retrieval GEMM with inline inter-chunk scan -------
// ret_c = A_c @ V_c + sum_{c'<c} QQ_c @ G_{c'}
// CTA 64x64 (MT=1), grid (4 colTiles, 2 rowTiles, 16 chunks) = 128 CTAs.
// ktiles: ti<8 -> (A_c, V_c); ti in [8*(cp+1), 8*(cp+2)) -> (QQ_c, G_cp).
__global__ void __launch_bounds__(256)
ret_gemm_kernel(const float* __restrict__ Amat, const float* __restrict__ Vm,
                const float* __restrict__ QQ,   const float* __restrict__ G,
                float* __restrict__ ret)
{
    const int z  = blockIdx.z;           // global chunk 0..15
    const int lc = z & 7;                // chunk within batch
    const long KD = (long)K2 * Dd;
    const float* Ab = Amat + (long)z * CH * CH;
    const float* Vb = Vm   + (long)z * CH * Dd;
    const float* Qb = QQ   + (long)z * CH * K2;
    const float* G0 = G    + (long)(z - lc) * KD;   // batch base
    float*       Cb = ret  + (long)z * CH * Dd;

    __shared__ __align__(16) float As[2][64 * 20];
    __shared__ __align__(16) float Bs[2][16 * 72];

    const int tid  = threadIdx.x;
    const int lane = tid & 31, wid = tid >> 5;
    const int wm = (wid & 3) * 16, wn = (wid >> 2) * 32;
    const int g = lane >> 2, t = lane & 3;
    const int rowTile = blockIdx.y * 64;
    const int colTile = blockIdx.x * 64;

    float c[1][4][4] = {};
    const int m = tid >> 2, akq = (tid & 3) * 4;
    const int bk = tid >> 4, bn = (tid & 15) * 4;
    float4 av, bv;

    const int T = 8 + 8 * lc;

    auto LDG = [&](int ti) {
        int k0 = (ti & 7) * 16;
        const float* Ap = (ti < 8) ? Ab : Qb;
        const float* Bp = (ti < 8) ? Vb : (G0 + (long)((ti >> 3) - 1) * KD);
        av = *(const float4*)&Ap[(long)(rowTile + m) * 128 + k0 + akq];
        bv = *(const float4*)&Bp[(long)(k0 + bk) * Dd + colTile + bn];
    };
    auto STS = [&](int s) {
        *(float4*)&As[s][m * 20 + akq] = tf32x4(av);
        *(float4*)&Bs[s][bk * 72 + bn] = tf32x4(bv);
    };

    LDG(0); STS(0); __syncthreads();
    #pragma unroll 1
    for (int ti = 0; ti < T; ti++) {
        if (ti + 1 < T) LDG(ti + 1);
        mma_mk<1>(As[ti & 1], Bs[ti & 1], wm, wn, g, t, c);
        if (ti + 1 < T) { STS((ti + 1) & 1); __syncthreads(); }
    }

    #pragma unroll
    for (int nt = 0; nt < 4; nt++) {
        int col = colTile + wn + nt * 8 + 2 * t;
        #pragma unroll
        for (int dr = 0; dr < 2; dr++) {
            int r = rowTile + wm + g + dr * 8;
            *(float2*)&Cb[(long)r * Dd + col] =
                make_float2(c[0][nt][dr * 2 + 0], c[0][nt][dr * 2 + 1]);
        }
    }
}

// ------------------------- final GEMM: out = x + rn@wo + bo ------------------
__global__ void __launch_bounds__(256)
final_gemm_kernel(const float* __restrict__ A, const float* __restrict__ W,
                  const float* __restrict__ bias, const float* __restrict__ extra,
                  float* __restrict__ C)
{
    __shared__ __align__(16) float As[2][64 * 20];
    __shared__ __align__(16) float Bs[2][16 * 72];

    const int tid  = threadIdx.x;
    const int lane = tid & 31, wid = tid >> 5;
    const int wm = (wid & 3) * 16, wn = (wid >> 2) * 32;
    const int g = lane >> 2, t = lane & 3;
    const int rowTile = blockIdx.y * 64;
    const int colTile = blockIdx.x * 64;

    float c[1][4][4] = {};
    const int m = tid >> 2, akq = (tid & 3) * 4;
    const int bk = tid >> 4, bn = (tid & 15) * 4;
    float4 av, bv;

    auto LDG = [&](int k0) {
        av = *(const float4*)&A[(long)(rowTile + m) * Dd + k0 + akq];
        bv = *(const float4*)&W[(long)(k0 + bk) * Dd + colTile + bn];
    };
    auto STS = [&](int s) {
        *(float4*)&As[s][m * 20 + akq] = tf32x4(av);
        *(float4*)&Bs[s][bk * 72 + bn] = tf32x4(bv);
    };

    LDG(0); STS(0); __syncthreads();
    #pragma unroll 1
    for (int ti = 0; ti < 16; ti++) {
        if (ti + 1 < 16) LDG((ti + 1) * 16);
        mma_mk<1>(As[ti & 1], Bs[ti & 1], wm, wn, g, t, c);
        if (ti + 1 < 16) { STS((ti + 1) & 1); __syncthreads(); }
    }

    #pragma unroll
    for (int nt = 0; nt < 4; nt++) {
        int col = colTile + wn + nt * 8 + 2 * t;
        #pragma unroll
        for (int dr = 0; dr < 2; dr++) {
            int r = rowTile + wm + g + dr * 8;
            float v0 = c[0][nt][dr * 2 + 0] + bias[col]
                     + extra[(long)r * Dd + col];
            float v1 = c[0][nt][dr * 2 + 1] + bias[col + 1]
                     + extra[(long)r * Dd + col + 1];
            *(float2*)&C[(long)r * Dd + col] = make_float2(v0, v1);
        }
    }
}

// ------------------------- layernorm ----------------------------------------
__global__ void ln_kernel(const float* __restrict__ ret,
                          const float* __restrict__ gg,
                          const float* __restrict__ bb,
                          float* __restrict__ rn)
{
    int n = blockIdx.x;
    int l = n % Ll;
    int d = threadIdx.x;      // 256 threads == D
    float v = ret[(long)n * Dd + d] * rsqrtf((float)(l + 1) * (float)Kk);

    float s = v, s2 = v * v;
    #pragma unroll
    for (int o = 16; o; o >>= 1) {
        s  += __shfl_xor_sync(0xffffffffu, s,  o);
        s2 += __shfl_xor_sync(0xffffffffu, s2, o);
    }
    __shared__ float ss[8], ss2[8];
    int w = d >> 5, lane = d & 31;
    if (lane == 0) { ss[w] = s; ss2[w] = s2; }
    __syncthreads();
    if (w == 0) {
        float a  = (lane < 8) ? ss[lane]  : 0.0f;
        float a2 = (lane < 8) ? ss2[lane] : 0.0f;
        #pragma unroll
        for (int o = 4; o; o >>= 1) {
            a  += __shfl_xor_sync(0xffffffffu, a,  o);
            a2 += __shfl_xor_sync(0xffffffffu, a2, o);
        }
        if (lane == 0) { ss[0] = a; ss2[0] = a2; }
    }
    __syncthreads();
    float mu  = ss[0] / Dd;
    float var = ss2[0] / Dd - mu * mu;
    rn[(long)n * Dd + d] = (v - mu) * rsqrtf(var + EPSv) * gg[d] + bb[d];
}

// ------------------------- host launcher ------------------------------------
extern "C" void kernel_launch(void* const* d_in, const int* in_sizes, int n_in,
                              void* d_out, int out_size)
{
    const float* x     = (const float*)d_in[0];
    const float* pos_k = (const float*)d_in[1];
    const float* w1_k  = (const float*)d_in[2];
    const float* b1_k  = (const float*)d_in[3];
    const float* w2_k  = (const float*)d_in[4];
    const float* b2_k  = (const float*)d_in[5];
    const float* wa_k  = (const float*)d_in[6];
    const float* ba_k  = (const float*)d_in[7];
    const float* pos_q = (const float*)d_in[8];
    const float* w1_q  = (const float*)d_in[9];
    const float* b1_q  = (const float*)d_in[10];
    const float* w2_q  = (const float*)d_in[11];
    const float* b2_q  = (const float*)d_in[12];
    const float* wa_q  = (const float*)d_in[13];
    const float* ba_q  = (const float*)d_in[14];
    const float* wv    = (const float*)d_in[15];
    const float* bv    = (const float*)d_in[16];
    const float* ln_g  = (const float*)d_in[17];
    const float* ln_b  = (const float*)d_in[18];
    const float* wo    = (const float*)d_in[19];
    const float* bo    = (const float*)d_in[20];
    float* out = (float*)d_out;

    float *hk, *hq, *kk, *qq, *V, *G, *Amat, *ret, *rn;
    cudaGetSymbolAddress((void**)&hk,   g_hk);
    cudaGetSymbolAddress((void**)&hq,   g_hq);
    cudaGetSymbolAddress((void**)&kk,   g_kk);
    cudaGetSymbolAddress((void**)&qq,   g_qq);
    cudaGetSymbolAddress((void**)&V,    g_V);
    cudaGetSymbolAddress((void**)&G,    g_G);
    cudaGetSymbolAddress((void**)&Amat, g_A);
    cudaGetSymbolAddress((void**)&ret,  g_ret);
    cudaGetSymbolAddress((void**)&rn,   g_rn);

    // 1. hk = gelu((x+pos_k)@w1_k+b1), hq likewise, V = x@wv+bv  (384 CTAs)
    enc_gemm_kernel<<<dim3(4, 32, 3), 256>>>(x, pos_k, pos_q,
                                             w1_k, b1_k, w1_q, b1_q, wv, bv,
                                             hk, hq, V);

    // 2. fused head GEMMs + phasor -> kk, qq  (64 CTAs)
    phasor_gemm_kernel<<<dim3(1, 32, 2), 256>>>(x, pos_k, pos_q, hk, hq,
                                                w2_k, b2_k, wa_k, ba_k,
                                                w2_q, b2_q, wa_q, ba_q,
                                                kk, qq);

    // 3. merged: G = KK^T V (128 CTAs) + A = tril(QQ KK^T) (64 CTAs)
    gamask_kernel<<<dim3(1, 1, 192), 256>>>(kk, qq, V, G, Amat);

    // 4. ret_c = A_c @ V_c + sum_{c'<c} QQ_c @ G_c'  (128 CTAs, inline scan)
    ret_gemm_kernel<<<dim3(4, 2, NCH), 256>>>(Amat, V, qq, G, ret);

    // 5. normalize + layernorm
    ln_kernel<<<NTOK, 256>>>(ret, ln_g, ln_b, rn);

    // 6. out = x + rn @ wo + bo  (128 CTAs)
    final_gemm_kernel<<<dim3(4, 32), 256>>>(rn, wo, bo, x, out);
}

// round 17
// speedup vs baseline: 1.7605x; 1.7605x over previous
#include <cuda_runtime.h>
#include <math.h>
#include <stdint.h>

#define Bb   2
#define Ll   1024
#define Dd   256
#define Kk   64
#define K2   128          // 2K (re|im concat)
#define NTOK (Bb*Ll)      // 2048
#define CH   128          // scan chunk length
#define NC   (Ll/CH)      // 8
#define NCH  (Bb*NC)      // 16
#define EPSv 1e-5f
#define PIv  3.14159265358979323846f

// ------------------------- scratch (static device memory) -------------------
__device__ float g_hk  [NTOK*Dd];
__device__ float g_hq  [NTOK*Dd];
__device__ float g_kk  [NTOK*K2];
__device__ float g_qq  [NTOK*K2];
__device__ float g_V   [NTOK*Dd];
__device__ float g_G   [NCH*K2*Dd];
__device__ float g_S   [NCH*K2*Dd];
__device__ float g_A   [NCH*CH*CH];
__device__ float g_ret [NTOK*Dd];
__device__ float g_rn  [NTOK*Dd];

// ------------------------- tf32 mma primitives ------------------------------
__device__ __forceinline__ float to_tf32(float x) {
    uint32_t u;
    asm("cvt.rna.tf32.f32 %0, %1;" : "=r"(u) : "f"(x));
    return __uint_as_float(u);
}
__device__ __forceinline__ float4 tf32x4(float4 v) {
    return make_float4(to_tf32(v.x), to_tf32(v.y), to_tf32(v.z), to_tf32(v.w));
}

__device__ __forceinline__ void mma8(float c[4], const uint32_t a[4], const uint32_t b[2]) {
    asm volatile(
        "mma.sync.aligned.m16n8k8.row.col.f32.tf32.tf32.f32 "
        "{%0,%1,%2,%3}, {%4,%5,%6,%7}, {%8,%9}, {%0,%1,%2,%3};"
        : "+f"(c[0]), "+f"(c[1]), "+f"(c[2]), "+f"(c[3])
        : "r"(a[0]), "r"(a[1]), "r"(a[2]), "r"(a[3]), "r"(b[0]), "r"(b[1]));
}

// ---- cp.async helpers ------------------------------------------------------
__device__ __forceinline__ void cp16(void* smem_ptr, const void* gptr) {
    uint32_t sa = (uint32_t)__cvta_generic_to_shared(smem_ptr);
    asm volatile("cp.async.cg.shared.global [%0], [%1], 16;" :: "r"(sa), "l"(gptr));
}
__device__ __forceinline__ void cp_commit() {
    asm volatile("cp.async.commit_group;");
}
__device__ __forceinline__ void cp_wait2() {
    asm volatile("cp.async.wait_group 2;");
}

// ---- A in [m][20] row-major, B in [k][72] k-major (conflict-free frags) ----
template<int MT>
__device__ __forceinline__ void mma_mk(const float* As, const float* Bs,
                                       int wm, int wn, int g, int t, float (*c)[4][4])
{
    #pragma unroll
    for (int ks = 0; ks < 16; ks += 8) {
        uint32_t a[MT][4], b[4][2];
        #pragma unroll
        for (int mt = 0; mt < MT; mt++) {
            int m0 = wm + mt * 16 + g;
            a[mt][0] = __float_as_uint(As[m0 * 20 + ks + t]);
            a[mt][1] = __float_as_uint(As[(m0 + 8) * 20 + ks + t]);
            a[mt][2] = __float_as_uint(As[m0 * 20 + ks + t + 4]);
            a[mt][3] = __float_as_uint(As[(m0 + 8) * 20 + ks + t + 4]);
        }
        #pragma unroll
        for (int nt = 0; nt < 4; nt++) {
            int n0 = wn + nt * 8 + g;
            b[nt][0] = __float_as_uint(Bs[(ks + t) * 72 + n0]);
            b[nt][1] = __float_as_uint(Bs[(ks + t + 4) * 72 + n0]);
        }
        #pragma unroll
        for (int mt = 0; mt < MT; mt++)
            #pragma unroll
            for (int nt = 0; nt < 4; nt++)
                mma8(c[mt][nt], a[mt], b[nt]);
    }
}

// ---- same as mma_mk but smem holds raw fp32; cvt.rna applied at frag load --
template<int MT>
__device__ __forceinline__ void mma_mk_cvt(const float* As, const float* Bs,
                                           int wm, int wn, int g, int t, float (*c)[4][4])
{
    #pragma unroll
    for (int ks = 0; ks < 16; ks += 8) {
        uint32_t a[MT][4], b[4][2];
        #pragma unroll
        for (int mt = 0; mt < MT; mt++) {
            int m0 = wm + mt * 16 + g;
            a[mt][0] = __float_as_uint(to_tf32(As[m0 * 20 + ks + t]));
            a[mt][1] = __float_as_uint(to_tf32(As[(m0 + 8) * 20 + ks + t]));
            a[mt][2] = __float_as_uint(to_tf32(As[m0 * 20 + ks + t + 4]));
            a[mt][3] = __float_as_uint(to_tf32(As[(m0 + 8) * 20 + ks + t + 4]));
        }
        #pragma unroll
        for (int nt = 0; nt < 4; nt++) {
            int n0 = wn + nt * 8 + g;
            b[nt][0] = __float_as_uint(to_tf32(Bs[(ks + t) * 72 + n0]));
            b[nt][1] = __float_as_uint(to_tf32(Bs[(ks + t + 4) * 72 + n0]));
        }
        #pragma unroll
        for (int mt = 0; mt < MT; mt++)
            #pragma unroll
            for (int nt = 0; nt < 4; nt++)
                mma8(c[mt][nt], a[mt], b[nt]);
    }
}

// ---- A in [m][20], B in [n][20] (transposed-B operand) ---------------------
template<int MT>
__device__ __forceinline__ void mma_mk_tb(const float* As, const float* Bs,
                                          int wm, int wn, int g, int t, float (*c)[4][4])
{
    #pragma unroll
    for (int ks = 0; ks < 16; ks += 8) {
        uint32_t a[MT][4], b[4][2];
        #pragma unroll
        for (int mt = 0; mt < MT; mt++) {
            int m0 = wm + mt * 16 + g;
            a[mt][0] = __float_as_uint(As[m0 * 20 + ks + t]);
            a[mt][1] = __float_as_uint(As[(m0 + 8) * 20 + ks + t]);
            a[mt][2] = __float_as_uint(As[m0 * 20 + ks + t + 4]);
            a[mt][3] = __float_as_uint(As[(m0 + 8) * 20 + ks + t + 4]);
        }
        #pragma unroll
        for (int nt = 0; nt < 4; nt++) {
            int n0 = wn + nt * 8 + g;
            b[nt][0] = __float_as_uint(Bs[n0 * 20 + ks + t]);
            b[nt][1] = __float_as_uint(Bs[n0 * 20 + ks + t + 4]);
        }
        #pragma unroll
        for (int mt = 0; mt < MT; mt++)
            #pragma unroll
            for (int nt = 0; nt < 4; nt++)
                mma8(c[mt][nt], a[mt], b[nt]);
    }
}

// ---- both operands [k][LD] k-major -----------------------------------------
template<int MT, int LDA, int LDB>
__device__ __forceinline__ void mma_kk(const float* As, const float* Bs,
                                       int wm, int wn, int g, int t, float (*c)[4][4])
{
    #pragma unroll
    for (int ks = 0; ks < 16; ks += 8) {
        uint32_t a[MT][4], b[4][2];
        #pragma unroll
        for (int mt = 0; mt < MT; mt++) {
            int m0 = wm + mt * 16 + g;
            a[mt][0] = __float_as_uint(As[(ks + t) * LDA + m0]);
            a[mt][1] = __float_as_uint(As[(ks + t) * LDA + m0 + 8]);
            a[mt][2] = __float_as_uint(As[(ks + t + 4) * LDA + m0]);
            a[mt][3] = __float_as_uint(As[(ks + t + 4) * LDA + m0 + 8]);
        }
        #pragma unroll
        for (int nt = 0; nt < 4; nt++) {
            int n0 = wn + nt * 8 + g;
            b[nt][0] = __float_as_uint(Bs[(ks + t) * LDB + n0]);
            b[nt][1] = __float_as_uint(Bs[(ks + t + 4) * LDB + n0]);
        }
        #pragma unroll
        for (int mt = 0; mt < MT; mt++)
            #pragma unroll
            for (int nt = 0; nt < 4; nt++)
                mma8(c[mt][nt], a[mt], b[nt]);
    }
}

// ------------------------- encoder pre-GEMM (z=3)  [R14-validated] -----------
// CTA 128x64, 256 threads, 8 warps of 32x32 (MT=2). ktile 16, double-buffered.
__global__ void __launch_bounds__(256)
enc_gemm_kernel(const float* __restrict__ x,
                const float* __restrict__ pos_k, const float* __restrict__ pos_q,
                const float* __restrict__ w1_k, const float* __restrict__ b1_k,
                const float* __restrict__ w1_q, const float* __restrict__ b1_q,
                const float* __restrict__ wv,   const float* __restrict__ bv,
                float* __restrict__ hk, float* __restrict__ hq, float* __restrict__ V)
{
    const int z = blockIdx.z;
    const float* W;  const float* bias; const float* pos; float* C;
    if (z == 0)      { W = w1_k; bias = b1_k; pos = pos_k; C = hk; }
    else if (z == 1) { W = w1_q; bias = b1_q; pos = pos_q; C = hq; }
    else             { W = wv;   bias = bv;   pos = nullptr; C = V; }

    __shared__ __align__(16) float As[2][128 * 20];
    __shared__ __align__(16) float Bs[2][16 * 72];

    const int tid  = threadIdx.x;
    const int lane = tid & 31, wid = tid >> 5;
    const int wm = (wid & 3) * 32, wn = (wid >> 2) * 32;
    const int g = lane >> 2, t = lane & 3;
    const int rowTile = blockIdx.y * 128;
    const int colTile = blockIdx.x * 64;

    float c[2][4][4] = {};
    float4 a0, a1, b0;
    const int m = tid >> 1, kq = (tid & 1) * 8;
    const int row = rowTile + m;
    const int prow = row & (Ll - 1);
    const int bk = tid >> 4, bn = (tid & 15) * 4;

    auto LDG = [&](int k0) {
        a0 = *(const float4*)&x[(long)row * Dd + k0 + kq];
        a1 = *(const float4*)&x[(long)row * Dd + k0 + kq + 4];
        if (pos) {
            float4 p0 = *(const float4*)&pos[(long)prow * Dd + k0 + kq];
            float4 p1 = *(const float4*)&pos[(long)prow * Dd + k0 + kq + 4];
            a0.x += p0.x; a0.y += p0.y; a0.z += p0.z; a0.w += p0.w;
            a1.x += p1.x; a1.y += p1.y; a1.z += p1.z; a1.w += p1.w;
        }
        b0 = *(const float4*)&W[(long)(k0 + bk) * Dd + colTile + bn];
    };
    auto STS = [&](int s) {
        *(float4*)&As[s][m * 20 + kq]     = tf32x4(a0);
        *(float4*)&As[s][m * 20 + kq + 4] = tf32x4(a1);
        *(float4*)&Bs[s][bk * 72 + bn]    = tf32x4(b0);
    };

    LDG(0); STS(0); __syncthreads();
    #pragma unroll 1
    for (int ti = 0; ti < 16; ti++) {
        if (ti + 1 < 16) LDG((ti + 1) * 16);
        mma_mk<2>(As[ti & 1], Bs[ti & 1], wm, wn, g, t, c);
        if (ti + 1 < 16) { STS((ti + 1) & 1); __syncthreads(); }
    }

    #pragma unroll
    for (int mt = 0; mt < 2; mt++)
        #pragma unroll
        for (int nt = 0; nt < 4; nt++) {
            int col = colTile + wn + nt * 8 + 2 * t;
            #pragma unroll
            for (int dr = 0; dr < 2; dr++) {
                int r = rowTile + wm + mt * 16 + g + dr * 8;
                float v0 = c[mt][nt][dr * 2 + 0] + bias[col];
                float v1 = c[mt][nt][dr * 2 + 1] + bias[col + 1];
                if (z < 2) {
                    v0 = 0.5f * v0 * (1.0f + erff(v0 * 0.70710678118654752440f));
                    v1 = 0.5f * v1 * (1.0f + erff(v1 * 0.70710678118654752440f));
                }
                *(float2*)&C[(long)r * Dd + col] = make_float2(v0, v1);
            }
        }
}

// ------------------------- fused head GEMMs + phasor (z=2) [R14] -------------
struct P4 { float4 u; };
__device__ __forceinline__ void ldgB_kn(P4& p, const float* __restrict__ B,
                                        int ld, int colTile, int k0, int tid) {
    int k = tid >> 4, nq = (tid & 15) * 4;
    p.u = *(const float4*)&B[(long)(k0 + k) * ld + colTile + nq];
}
__device__ __forceinline__ void stsB_kn68(float* Bs, const P4& p, int tid) {
    int k = tid >> 4, nq = (tid & 15) * 4;
    *(float4*)&Bs[k * 68 + nq] = tf32x4(p.u);
}

__global__ void __launch_bounds__(256)
phasor_gemm_kernel(const float* __restrict__ x,
                   const float* __restrict__ pos_k, const float* __restrict__ pos_q,
                   const float* __restrict__ hk,   const float* __restrict__ hq,
                   const float* __restrict__ w2_k, const float* __restrict__ b2_k,
                   const float* __restrict__ wa_k, const float* __restrict__ ba_k,
                   const float* __restrict__ w2_q, const float* __restrict__ b2_q,
                   const float* __restrict__ wa_q, const float* __restrict__ ba_q,
                   float* __restrict__ kk, float* __restrict__ qq)
{
    const int z = blockIdx.z;
    const float* h   = z ? hq    : hk;
    const float* pos = z ? pos_q : pos_k;
    const float* W2  = z ? w2_q  : w2_k;
    const float* B2  = z ? b2_q  : b2_k;
    const float* Wa  = z ? wa_q  : wa_k;
    const float* Ba  = z ? ba_q  : ba_k;
    float* out       = z ? qq    : kk;

    __shared__ __align__(16) float Ah[2][16 * 68];
    __shared__ __align__(16) float Ax[2][16 * 68];
    __shared__ __align__(16) float Bp[2][16 * 68];
    __shared__ __align__(16) float Bm[2][16 * 68];

    const int tid  = threadIdx.x;
    const int lane = tid & 31, wid = tid >> 5;
    const int wm = (wid & 3) * 16, wn = (wid >> 2) * 32;
    const int g = lane >> 2, t = lane & 3;
    const int rowTile = blockIdx.y * 64;

    float cP[1][4][4] = {};
    float cA[1][4][4] = {};

    const int am = tid >> 2, akq = (tid & 3) * 4;
    const int arow = rowTile + am;
    const int prow = arow & (Ll - 1);
    float4 vh, vx, vp; P4 p2, pm;

    auto LDG = [&](int k0) {
        vh = *(const float4*)&h[(long)arow * Dd + k0 + akq];
        vx = *(const float4*)&x[(long)arow * Dd + k0 + akq];
        vp = *(const float4*)&pos[(long)prow * Dd + k0 + akq];
        ldgB_kn(p2, W2, Kk, 0, k0, tid);
        ldgB_kn(pm, Wa, Kk, 0, k0, tid);
    };
    auto STS = [&](int nb) {
        Ah[nb][(akq + 0) * 68 + am] = to_tf32(vh.x);
        Ah[nb][(akq + 1) * 68 + am] = to_tf32(vh.y);
        Ah[nb][(akq + 2) * 68 + am] = to_tf32(vh.z);
        Ah[nb][(akq + 3) * 68 + am] = to_tf32(vh.w);
        Ax[nb][(akq + 0) * 68 + am] = to_tf32(vx.x + vp.x);
        Ax[nb][(akq + 1) * 68 + am] = to_tf32(vx.y + vp.y);
        Ax[nb][(akq + 2) * 68 + am] = to_tf32(vx.z + vp.z);
        Ax[nb][(akq + 3) * 68 + am] = to_tf32(vx.w + vp.w);
        stsB_kn68(Bp[nb], p2, tid);
        stsB_kn68(Bm[nb], pm, tid);
    };

    LDG(0); STS(0);
    __syncthreads();

    const int T = Dd >> 4;
    #pragma unroll 1
    for (int ti = 0; ti < T; ti++) {
        if (ti + 1 < T) LDG((ti + 1) << 4);
        mma_kk<1, 68, 68>(Ah[ti & 1], Bp[ti & 1], wm, wn, g, t, cP);
        mma_kk<1, 68, 68>(Ax[ti & 1], Bm[ti & 1], wm, wn, g, t, cA);
        if (ti + 1 < T) { STS((ti + 1) & 1); __syncthreads(); }
    }

    #pragma unroll
    for (int nt = 0; nt < 4; nt++) {
        int col = wn + nt * 8 + 2 * t;
        #pragma unroll
        for (int dr = 0; dr < 2; dr++) {
            int n = rowTile + wm + g + dr * 8;
            #pragma unroll
            for (int dc = 0; dc < 2; dc++) {
                int cc = col + dc;
                float p = cP[0][nt][dr * 2 + dc] + B2[cc];
                float a = cA[0][nt][dr * 2 + dc] + Ba[cc];
                float ph = tanhf(p) * PIv;
                float sp = fmaxf(a, 0.0f) + log1pf(expf(-fabsf(a)));
                float amp = sp + 0.1f;
                float s, cs;
                sincosf(ph, &s, &cs);
                out[(long)n * K2 + cc]      = amp * cs;
                out[(long)n * K2 + Kk + cc] = amp * s;
            }
        }
    }
}

// ------------------------- merged G + masked-A kernel (192 CTAs) [R14] -------
__global__ void __launch_bounds__(256)
gamask_kernel(const float* __restrict__ kk, const float* __restrict__ qq,
              const float* __restrict__ V,
              float* __restrict__ G, float* __restrict__ Amat)
{
    __shared__ __align__(16) float SA[2][1280];
    __shared__ __align__(16) float SB[2][1280];

    const int tid  = threadIdx.x;
    const int lane = tid & 31, wid = tid >> 5;
    const int wm = (wid & 3) * 16, wn = (wid >> 2) * 32;
    const int g = lane >> 2, t = lane & 3;
    const int z = blockIdx.z;

    if (z < 128) {
        const int chunk = z >> 3, sub = z & 7;
        const int r0 = (sub >> 2) * 64;        // K2 half
        const int colTile = (sub & 3) * 64;    // D slice
        const float* Kb = kk + (long)chunk * CH * K2;
        const float* Vb = V  + (long)chunk * CH * Dd;
        float*       Gb = G  + (long)chunk * K2 * Dd;

        float c[1][4][4] = {};
        const int k = tid >> 4, aq = (tid & 15) * 4;
        float4 av, bv;

        auto LDG = [&](int k0) {
            av = *(const float4*)&Kb[(long)(k0 + k) * K2 + r0 + aq];
            bv = *(const float4*)&Vb[(long)(k0 + k) * Dd + colTile + aq];
        };
        auto STS = [&](int s) {
            *(float4*)&SA[s][k * 72 + aq] = tf32x4(av);
            *(float4*)&SB[s][k * 72 + aq] = tf32x4(bv);
        };

        LDG(0); STS(0); __syncthreads();
        #pragma unroll 1
        for (int ti = 0; ti < 8; ti++) {
            if (ti + 1 < 8) LDG((ti + 1) * 16);
            mma_kk<1, 72, 72>(SA[ti & 1], SB[ti & 1], wm, wn, g, t, c);
            if (ti + 1 < 8) { STS((ti + 1) & 1); __syncthreads(); }
        }

        #pragma unroll
        for (int nt = 0; nt < 4; nt++) {
            int col = colTile + wn + nt * 8 + 2 * t;
            #pragma unroll
            for (int dr = 0; dr < 2; dr++) {
                int r = r0 + wm + g + dr * 8;
                *(float2*)&Gb[(long)r * Dd + col] =
                    make_float2(c[0][nt][dr * 2 + 0], c[0][nt][dr * 2 + 1]);
            }
        }
    } else {
        const int idx = z - 128;
        const int chunk = idx >> 2, sub = idx & 3;
        const int rowTile = (sub >> 1) * 64;
        const int colTile = (sub & 1) * 64;
        const float* Qb = qq + (long)chunk * CH * K2;
        const float* Kb = kk + (long)chunk * CH * K2;
        float*       Cb = Amat + (long)chunk * CH * CH;

        float c[1][4][4] = {};
        const int m = tid >> 2, kq = (tid & 3) * 4;
        float4 av, bv;

        auto LDG = [&](int k0) {
            av = *(const float4*)&Qb[(long)(rowTile + m) * K2 + k0 + kq];
            bv = *(const float4*)&Kb[(long)(colTile + m) * K2 + k0 + kq];
        };
        auto STS = [&](int s) {
            *(float4*)&SA[s][m * 20 + kq] = tf32x4(av);
            *(float4*)&SB[s][m * 20 + kq] = tf32x4(bv);
        };

        LDG(0); STS(0); __syncthreads();
        #pragma unroll 1
        for (int ti = 0; ti < 8; ti++) {
            if (ti + 1 < 8) LDG((ti + 1) * 16);
            mma_mk_tb<1>(SA[ti & 1], SB[ti & 1], wm, wn, g, t, c);
            if (ti + 1 < 8) { STS((ti + 1) & 1); __syncthreads(); }
        }

        #pragma unroll
        for (int nt = 0; nt < 4; nt++) {
            int col = colTile + wn + nt * 8 + 2 * t;
            #pragma unroll
            for (int dr = 0; dr < 2; dr++) {
                int r = rowTile + wm + g + dr * 8;
                float v0 = (col     > r) ? 0.0f : c[0][nt][dr * 2 + 0];
                float v1 = (col + 1 > r) ? 0.0f : c[0][nt][dr * 2 + 1];
                *(float2*)&Cb[(long)r * CH + col] = make_float2(v0, v1);
            }
        }
    }
}

// ------------------------- retrieval GEMM (cp.async 4-stage) -----------------
// ret_c = A_c @ V_c + QQ_c @ S_c ; CTA 64x64 (MT=1), 128 CTAs, 16 ktiles.
__global__ void __launch_bounds__(256)
ret_gemm_kernel(const float* __restrict__ Amat, const float* __restrict__ Vm,
                const float* __restrict__ QQ,   const float* __restrict__ S,
                float* __restrict__ ret)
{
    const int z = blockIdx.z;
    const float* Ab = Amat + (long)z * CH * CH;
    const float* Vb = Vm   + (long)z * CH * Dd;
    const float* Qb = QQ   + (long)z * CH * K2;
    const float* Sb = S    + (long)z * K2 * Dd;
    float*       Cb = ret  + (long)z * CH * Dd;

    __shared__ __align__(16) float As[4][64 * 20];
    __shared__ __align__(16) float Bs[4][16 * 72];

    const int tid  = threadIdx.x;
    const int lane = tid & 31, wid = tid >> 5;
    const int wm = (wid & 3) * 16, wn = (wid >> 2) * 32;
    const int g = lane >> 2, t = lane & 3;
    const int rowTile = blockIdx.y * 64;
    const int colTile = blockIdx.x * 64;

    float c[1][4][4] = {};
    const int m = tid >> 2, akq = (tid & 3) * 4;
    const int bk = tid >> 4, bn = (tid & 15) * 4;

    auto ISSUE = [&](int ti) {
        int s = ti & 3;
        int k0 = (ti & 7) * 16;
        const float* Ap = (ti < 8) ? Ab : Qb;
        const float* Bp = (ti < 8) ? Vb : Sb;
        cp16(&As[s][m * 20 + akq], &Ap[(long)(rowTile + m) * 128 + k0 + akq]);
        cp16(&Bs[s][bk * 72 + bn], &Bp[(long)(k0 + bk) * Dd + colTile + bn]);
    };

    ISSUE(0); cp_commit();
    ISSUE(1); cp_commit();
    ISSUE(2); cp_commit();

    #pragma unroll 1
    for (int ti = 0; ti < 16; ti++) {
        cp_wait2();
        __syncthreads();
        if (ti + 3 < 16) ISSUE(ti + 3);
        cp_commit();
        mma_mk_cvt<1>(As[ti & 3], Bs[ti & 3], wm, wn, g, t, c);
    }

    #pragma unroll
    for (int nt = 0; nt < 4; nt++) {
        int col = colTile + wn + nt * 8 + 2 * t;
        #pragma unroll
        for (int dr = 0; dr < 2; dr++) {
            int r = rowTile + wm + g + dr * 8;
            *(float2*)&Cb[(long)r * Dd + col] =
                make_float2(c[0][nt][dr * 2 + 0], c[0][nt][dr * 2 + 1]);
        }
    }
}

// ------------------------- final GEMM (cp.async 4-stage) ---------------------
// out = x + rn@wo + bo ; CTA 64x64 (MT=1), grid (4, 32) = 128 CTAs.
__global__ void __launch_bounds__(256)
final_gemm_kernel(const float* __restrict__ A, const float* __restrict__ W,
                  const float* __restrict__ bias, const float* __restrict__ extra,
                  float* __restrict__ C)
{
    __shared__ __align__(16) float As[4][64 * 20];
    __shared__ __align__(16) float Bs[4][16 * 72];

    const int tid  = threadIdx.x;
    const int lane = tid & 31, wid = tid >> 5;
    const int wm = (wid & 3) * 16, wn = (wid >> 2) * 32;
    const int g = lane >> 2, t = lane & 3;
    const int rowTile = blockIdx.y * 64;
    const int colTile = blockIdx.x * 64;

    float c[1][4][4] = {};
    const int m = tid >> 2, akq = (tid & 3) * 4;
    const int bk = tid >> 4, bn = (tid & 15) * 4;

    auto ISSUE = [&](int ti) {
        int s = ti & 3;
        int k0 = ti * 16;
        cp16(&As[s][m * 20 + akq], &A[(long)(rowTile + m) * Dd + k0 + akq]);
        cp16(&Bs[s][bk * 72 + bn], &W[(long)(k0 + bk) * Dd + colTile + bn]);
    };

    ISSUE(0); cp_commit();
    ISSUE(1); cp_commit();
    ISSUE(2); cp_commit();

    #pragma unroll 1
    for (int ti = 0; ti < 16; ti++) {
        cp_wait2();
        __syncthreads();
        if (ti + 3 < 16) ISSUE(ti + 3);
        cp_commit();
        mma_mk_cvt<1>(As[ti & 3], Bs[ti & 3], wm, wn, g, t, c);
    }

    #pragma unroll
    for (int nt = 0; nt < 4; nt++) {
        int col = colTile + wn + nt * 8 + 2 * t;
        #pragma unroll
        for (int dr = 0; dr < 2; dr++) {
            int r = rowTile + wm + g + dr * 8;
            float v0 = c[0][nt][dr * 2 + 0] + bias[col]
                     + extra[(long)r * Dd + col];
            float v1 = c[0][nt][dr * 2 + 1] + bias[col + 1]
                     + extra[(long)r * Dd + col + 1];
            *(float2*)&C[(long)r * Dd + col] = make_float2(v0, v1);
        }
    }
}

// ------------------------- small kernels [R14] -------------------------------
// exclusive prefix: one thread per (b, chunk, float4-element), redundant sums.
__global__ void prefix_kernel()
{
    const int KD4 = K2 * Dd / 4;   // 8192
    int idx = blockIdx.x * blockDim.x + threadIdx.x;
    if (idx >= Bb * NC * KD4) return;
    int r  = idx % KD4;
    int bc = idx / KD4;
    int cc = bc % NC;
    int b  = bc / NC;
    const float4* G4 = reinterpret_cast<const float4*>(g_G);
    float4*       S4 = reinterpret_cast<float4*>(g_S);
    float4 acc = make_float4(0.f, 0.f, 0.f, 0.f);
    for (int cp = 0; cp < cc; cp++) {
        float4 gv = G4[(long)(b * NC + cp) * KD4 + r];
        acc.x += gv.x; acc.y += gv.y; acc.z += gv.z; acc.w += gv.w;
    }
    S4[idx] = acc;
}

// normalize by sqrt((l+1)*K), layernorm
__global__ void ln_kernel(const float* __restrict__ ret,
                          const float* __restrict__ gg,
                          const float* __restrict__ bb,
                          float* __restrict__ rn)
{
    int n = blockIdx.x;
    int l = n % Ll;
    int d = threadIdx.x;      // 256 threads == D
    float v = ret[(long)n * Dd + d] * rsqrtf((float)(l + 1) * (float)Kk);

    float s = v, s2 = v * v;
    #pragma unroll
    for (int o = 16; o; o >>= 1) {
        s  += __shfl_xor_sync(0xffffffffu, s,  o);
        s2 += __shfl_xor_sync(0xffffffffu, s2, o);
    }
    __shared__ float ss[8], ss2[8];
    int w = d >> 5, lane = d & 31;
    if (lane == 0) { ss[w] = s; ss2[w] = s2; }
    __syncthreads();
    if (w == 0) {
        float a  = (lane < 8) ? ss[lane]  : 0.0f;
        float a2 = (lane < 8) ? ss2[lane] : 0.0f;
        #pragma unroll
        for (int o = 4; o; o >>= 1) {
            a  += __shfl_xor_sync(0xffffffffu, a,  o);
            a2 += __shfl_xor_sync(0xffffffffu, a2, o);
        }
        if (lane == 0) { ss[0] = a; ss2[0] = a2; }
    }
    __syncthreads();
    float mu  = ss[0] / Dd;
    float var = ss2[0] / Dd - mu * mu;
    rn[(long)n * Dd + d] = (v - mu) * rsqrtf(var + EPSv) * gg[d] + bb[d];
}

// ------------------------- host launcher ------------------------------------
extern "C" void kernel_launch(void* const* d_in, const int* in_sizes, int n_in,
                              void* d_out, int out_size)
{
    const float* x     = (const float*)d_in[0];
    const float* pos_k = (const float*)d_in[1];
    const float* w1_k  = (const float*)d_in[2];
    const float* b1_k  = (const float*)d_in[3];
    const float* w2_k  = (const float*)d_in[4];
    const float* b2_k  = (const float*)d_in[5];
    const float* wa_k  = (const float*)d_in[6];
    const float* ba_k  = (const float*)d_in[7];
    const float* pos_q = (const float*)d_in[8];
    const float* w1_q  = (const float*)d_in[9];
    const float* b1_q  = (const float*)d_in[10];
    const float* w2_q  = (const float*)d_in[11];
    const float* b2_q  = (const float*)d_in[12];
    const float* wa_q  = (const float*)d_in[13];
    const float* ba_q  = (const float*)d_in[14];
    const float* wv    = (const float*)d_in[15];
    const float* bv    = (const float*)d_in[16];
    const float* ln_g  = (const float*)d_in[17];
    const float* ln_b  = (const float*)d_in[18];
    const float* wo    = (const float*)d_in[19];
    const float* bo    = (const float*)d_in[20];
    float* out = (float*)d_out;

    float *hk, *hq, *kk, *qq, *V, *G, *S, *Amat, *ret, *rn;
    cudaGetSymbolAddress((void**)&hk,   g_hk);
    cudaGetSymbolAddress((void**)&hq,   g_hq);
    cudaGetSymbolAddress((void**)&kk,   g_kk);
    cudaGetSymbolAddress((void**)&qq,   g_qq);
    cudaGetSymbolAddress((void**)&V,    g_V);
    cudaGetSymbolAddress((void**)&G,    g_G);
    cudaGetSymbolAddress((void**)&S,    g_S);
    cudaGetSymbolAddress((void**)&Amat, g_A);
    cudaGetSymbolAddress((void**)&ret,  g_ret);
    cudaGetSymbolAddress((void**)&rn,   g_rn);

    // 1. hk = gelu((x+pos_k)@w1_k+b1), hq likewise, V = x@wv+bv  (192 CTAs)
    enc_gemm_kernel<<<dim3(4, 16, 3), 256>>>(x, pos_k, pos_q,
                                             w1_k, b1_k, w1_q, b1_q, wv, bv,
                                             hk, hq, V);

    // 2. fused head GEMMs + phasor -> kk, qq  (64 CTAs)
    phasor_gemm_kernel<<<dim3(1, 32, 2), 256>>>(x, pos_k, pos_q, hk, hq,
                                                w2_k, b2_k, wa_k, ba_k,
                                                w2_q, b2_q, wa_q, ba_q,
                                                kk, qq);

    // 3. merged: G = KK^T V (128 CTAs) + A = tril(QQ KK^T) (64 CTAs)
    gamask_kernel<<<dim3(1, 1, 192), 256>>>(kk, qq, V, G, Amat);

    // 4. exclusive prefix over chunks -> S
    prefix_kernel<<<(Bb * NC * (K2 * Dd / 4) + 255) / 256, 256>>>();

    // 5. ret_c = A_c @ V_c + QQ_c @ S_c  (128 CTAs, cp.async pipeline)
    ret_gemm_kernel<<<dim3(4, 2, NCH), 256>>>(Amat, V, qq, S, ret);

    // 6. normalize + layernorm
    ln_kernel<<<NTOK, 256>>>(ret, ln_g, ln_b, rn);

    // 7. out = x + rn @ wo + bo  (128 CTAs, cp.async pipeline)
    final_gemm_kernel<<<dim3(4, 32), 256>>>(rn, wo, bo, x, out);
}